// round 6
// baseline (speedup 1.0000x reference)
#include <cuda_runtime.h>
#include <cuda_bf16.h>
#include <cstdint>

// VACF via band-Gram, parallelogram tiling on mma.sync bf16.
// Fused f32->bf16 split conversion hidden under mma issue; 1 barrier/chunk;
// persistent chunk-balanced grid (296 CTAs); last-CTA finalize (no fin kernel).
// S[t] = sum_i x_i . x_{i+t}; x = hi + lo (bf16); 3 passes hh+hl+lh.

#define T_DIM 10000
#define D_DIM 3000
#define NTILE 79                 // row tiles of 128
#define NCHT  94                 // K chunks of 32 elems
#define UNITS (NTILE * NCHT)     // 7426
#define NCTA  296
#define W_MAX 100
#define RB    240                // rows per tile (128 + halo)
#define F32_B   (RB * 128)       // 30720 f32 staging
#define STRB    80               // bf16 smem row stride
#define HTILE_B (RB * STRB)      // 19200
#define STAGE_B (2 * HTILE_B)    // hi + lo
#define SMEM_B  (F32_B + 2 * STAGE_B)   // 107520

__device__ double g_band[128];       // zero-init; finalizer re-zeroes
__device__ unsigned g_done;          // zero-init; finalizer re-zeroes

__device__ __forceinline__ void ldsm4(unsigned a, unsigned& r0, unsigned& r1,
                                      unsigned& r2, unsigned& r3) {
    asm volatile("ldmatrix.sync.aligned.m8n8.x4.shared.b16 {%0,%1,%2,%3}, [%4];"
                 : "=r"(r0), "=r"(r1), "=r"(r2), "=r"(r3) : "r"(a));
}

__device__ __forceinline__ void mma16816(float* c, const unsigned* a, const unsigned* b) {
    asm("mma.sync.aligned.m16n8k16.row.col.f32.bf16.bf16.f32 "
        "{%0,%1,%2,%3}, {%4,%5,%6,%7}, {%8,%9}, {%0,%1,%2,%3};"
        : "+f"(c[0]), "+f"(c[1]), "+f"(c[2]), "+f"(c[3])
        : "r"(a[0]), "r"(a[1]), "r"(a[2]), "r"(a[3]), "r"(b[0]), "r"(b[1]));
}

#define CPA16Z(dst, src, z) \
    asm volatile("cp.async.cg.shared.global [%0], [%1], 16, %2;" \
                 :: "r"(dst), "l"(src), "r"(z))

__global__ __launch_bounds__(256, 2) void vacf_gram(const float* __restrict__ vel,
                                                    float* __restrict__ out, int W) {
    extern __shared__ __align__(128) char sm[];
    __shared__ float s_band[W_MAX];
    __shared__ int s_last;

    const int tid  = threadIdx.x;
    const int warp = tid >> 5;
    const int lane = tid & 31;
    const int gB   = blockIdx.x;

    const unsigned smu = (unsigned)__cvta_generic_to_shared(sm);
    const unsigned bf0 = smu + F32_B;

    if (tid < W_MAX) s_band[tid] = 0.f;

    const int rl = lane & 7, gg = lane >> 3;
    const int arow  = 16 * warp + rl + ((gg & 1) << 3);
    const int acol0 = (gg >> 1) << 3;
    const int brow0 = 16 * warp + rl + ((gg >> 1) << 3);
    const int bcol0 = (gg & 1) << 3;

    int u  = (int)(((long)gB * UNITS) / NCTA);
    const int u1 = (int)(((long)(gB + 1) * UNITS) / NCTA);

    float c[15][4];

    while (u < u1) {
        const int tile = u / NCHT;
        const int cbeg = u % NCHT;
        const int cend = (cbeg + (u1 - u) < NCHT) ? cbeg + (u1 - u) : NCHT;
        const int R0   = tile * 128;
        u += cend - cbeg;

        #pragma unroll
        for (int i = 0; i < 15; i++)
            #pragma unroll
            for (int q = 0; q < 4; q++) c[i][q] = 0.f;

        auto load_f32 = [&](int ci) {
            #pragma unroll
            for (int k = 0; k < 8; k++) {
                int sid = tid + (k << 8);
                if (sid < RB * 8) {
                    int row = sid >> 3;
                    int seg = sid & 7;
                    int gr  = R0 + row;
                    int c4  = ci * 8 + seg;
                    unsigned ok = (gr < T_DIM && c4 < (D_DIM / 4)) ? 16u : 0u;
                    const float* gp = vel + ((size_t)(gr < T_DIM ? gr : 0)) * D_DIM
                                          + (c4 < (D_DIM / 4) ? c4 : 0) * 4;
                    CPA16Z(smu + (unsigned)(row * 128 + seg * 16), gp, ok);
                }
            }
            asm volatile("cp.async.commit_group;" ::: "memory");
        };

        // convert f32 staging -> bf16 stage stw (hi/lo). No barrier inside.
        auto convert = [&](int stw) {
            const unsigned hib = F32_B + stw * STAGE_B;
            #pragma unroll
            for (int k = 0; k < 8; k++) {
                int sid = tid + (k << 8);
                if (sid < RB * 8) {
                    int row = sid >> 3;
                    int seg = sid & 7;
                    const float4 v = *reinterpret_cast<const float4*>(
                        sm + (row * 128 + seg * 16));
                    __nv_bfloat162 h01 = __float22bfloat162_rn(make_float2(v.x, v.y));
                    __nv_bfloat162 h23 = __float22bfloat162_rn(make_float2(v.z, v.w));
                    float l0 = v.x - __bfloat162float(h01.x);
                    float l1 = v.y - __bfloat162float(h01.y);
                    float l2 = v.z - __bfloat162float(h23.x);
                    float l3 = v.w - __bfloat162float(h23.y);
                    __nv_bfloat162 q01 = __float22bfloat162_rn(make_float2(l0, l1));
                    __nv_bfloat162 q23 = __float22bfloat162_rn(make_float2(l2, l3));
                    uint2 hh, ll;
                    hh.x = *reinterpret_cast<unsigned*>(&h01);
                    hh.y = *reinterpret_cast<unsigned*>(&h23);
                    ll.x = *reinterpret_cast<unsigned*>(&q01);
                    ll.y = *reinterpret_cast<unsigned*>(&q23);
                    unsigned off = (unsigned)(row * STRB + seg * 8);
                    *reinterpret_cast<uint2*>(sm + hib + off) = hh;
                    *reinterpret_cast<uint2*>(sm + hib + HTILE_B + off) = ll;
                }
            }
        };

        // ---- prologue: chunk cbeg converted into stage 0; load cbeg+1 ----
        load_f32(cbeg);
        asm volatile("cp.async.wait_group 0;" ::: "memory");
        __syncthreads();
        convert(0);
        __syncthreads();
        if (cbeg + 1 < cend) load_f32(cbeg + 1);

        for (int ci = cbeg; ci < cend; ci++) {
            const int st  = (ci - cbeg) & 1;
            const unsigned hib = bf0 + st * STAGE_B;
            const unsigned lob = hib + HTILE_B;
            const bool havenext = (ci + 1 < cend);

            #pragma unroll
            for (int ks = 0; ks < 2; ks++) {
                const int kk = ks * 16;
                unsigned ahi[4], alo[4];
                {
                    unsigned aoff = (unsigned)(arow * STRB + (kk + acol0) * 2);
                    ldsm4(hib + aoff, ahi[0], ahi[1], ahi[2], ahi[3]);
                    ldsm4(lob + aoff, alo[0], alo[1], alo[2], alo[3]);
                }
                #pragma unroll
                for (int njp = 0; njp < 8; njp++) {
                    // hide conversion inside ks=0 after 2 njp of mma
                    if (ks == 0 && njp == 2 && havenext) {
                        asm volatile("cp.async.wait_group 0;" ::: "memory");
                        convert(st ^ 1);
                    }
                    unsigned boff = (unsigned)((brow0 + njp * 16) * STRB + (kk + bcol0) * 2);
                    unsigned bhi[4], blo[4];
                    ldsm4(hib + boff, bhi[0], bhi[1], bhi[2], bhi[3]);
                    ldsm4(lob + boff, blo[0], blo[1], blo[2], blo[3]);
                    const int nj0 = njp * 2;
                    mma16816(c[nj0], ahi, &bhi[0]);
                    if (nj0 + 1 < 15) mma16816(c[nj0 + 1], ahi, &bhi[2]);
                    mma16816(c[nj0], ahi, &blo[0]);
                    if (nj0 + 1 < 15) mma16816(c[nj0 + 1], ahi, &blo[2]);
                    mma16816(c[nj0], alo, &bhi[0]);
                    if (nj0 + 1 < 15) mma16816(c[nj0 + 1], alo, &bhi[2]);
                }
            }

            // single barrier per chunk: convert STS visible, staging consumed,
            // all ldsm of stage[st] done (stage[st] is overwritten next iter).
            __syncthreads();
            if (ci + 2 < cend) load_f32(ci + 2);
        }

        // ---- segment epilogue: band extraction ----
        #pragma unroll
        for (int nj = 0; nj < 15; nj++)
            #pragma unroll
            for (int q = 0; q < 4; q++) {
                int t = nj * 8 + ((lane & 3) << 1) + (q & 1)
                      - (lane >> 2) - ((q >> 1) << 3);
                if (t >= 0 && t < W_MAX) atomicAdd(&s_band[t], c[nj][q]);
            }
        __syncthreads();
        if (tid < W_MAX) {
            atomicAdd(&g_band[tid], (double)s_band[tid]);
            s_band[tid] = 0.f;
        }
        __syncthreads();
    }

    // ---- completion protocol: last CTA finalizes ----
    if (tid == 0) {
        __threadfence();
        unsigned p = atomicAdd(&g_done, 1u);
        s_last = (p == NCTA - 1);
    }
    __syncthreads();
    if (s_last) {
        __threadfence();
        if (tid < W_MAX && tid < W)
            out[tid] = (float)(g_band[tid] / ((double)(T_DIM - tid) * (double)D_DIM));
        if (tid < 128) g_band[tid] = 0.0;
        if (tid == 0) g_done = 0;
    }
}

extern "C" void kernel_launch(void* const* d_in, const int* in_sizes, int n_in,
                              void* d_out, int out_size) {
    const float* vel = (const float*)d_in[0];
    cudaFuncSetAttribute(vacf_gram, cudaFuncAttributeMaxDynamicSharedMemorySize, SMEM_B);
    vacf_gram<<<NCTA, 256, SMEM_B>>>(vel, (float*)d_out, out_size);
}

// round 7
// speedup vs baseline: 1.0474x; 1.0474x over previous
#include <cuda_runtime.h>
#include <cuda_bf16.h>
#include <cstdint>

// VACF via band-Gram, parallelogram tiling on mma.sync bf16.
// Per-thread staging (cp.async slot == convert slot) -> convert needs no barrier.
// One __syncthreads per chunk. Persistent chunk-balanced grid, last-CTA finalize.
// S[t] = sum_i x_i . x_{i+t}; x = hi + lo (bf16); 3 passes hh+hl+lh.

#define T_DIM 10000
#define D_DIM 3000
#define NTILE 79                 // row tiles of 128
#define NCHT  94                 // K chunks of 32 elems
#define UNITS (NTILE * NCHT)     // 7426
#define NCTA  296
#define W_MAX 100
#define RB    240                // rows per tile (128 + halo)
#define F32_B   (RB * 128)       // 30720 f32 staging
#define STRB    80               // bf16 smem row stride
#define HTILE_B (RB * STRB)      // 19200
#define STAGE_B (2 * HTILE_B)    // hi + lo
#define SMEM_B  (F32_B + 2 * STAGE_B)   // 107520

__device__ double g_band[128];       // zero-init; finalizer re-zeroes
__device__ unsigned g_done;          // zero-init; finalizer re-zeroes

__device__ __forceinline__ void ldsm4(unsigned a, unsigned& r0, unsigned& r1,
                                      unsigned& r2, unsigned& r3) {
    asm volatile("ldmatrix.sync.aligned.m8n8.x4.shared.b16 {%0,%1,%2,%3}, [%4];"
                 : "=r"(r0), "=r"(r1), "=r"(r2), "=r"(r3) : "r"(a));
}

__device__ __forceinline__ void mma16816(float* c, const unsigned* a, const unsigned* b) {
    asm("mma.sync.aligned.m16n8k16.row.col.f32.bf16.bf16.f32 "
        "{%0,%1,%2,%3}, {%4,%5,%6,%7}, {%8,%9}, {%0,%1,%2,%3};"
        : "+f"(c[0]), "+f"(c[1]), "+f"(c[2]), "+f"(c[3])
        : "r"(a[0]), "r"(a[1]), "r"(a[2]), "r"(a[3]), "r"(b[0]), "r"(b[1]));
}

#define CPA16Z(dst, src, z) \
    asm volatile("cp.async.cg.shared.global [%0], [%1], 16, %2;" \
                 :: "r"(dst), "l"(src), "r"(z))

__global__ __launch_bounds__(256, 2) void vacf_gram(const float* __restrict__ vel,
                                                    float* __restrict__ out, int W) {
    extern __shared__ __align__(128) char sm[];
    __shared__ float s_band[W_MAX];
    __shared__ int s_last;

    const int tid  = threadIdx.x;
    const int warp = tid >> 5;
    const int lane = tid & 31;
    const int gB   = blockIdx.x;

    const unsigned smu = (unsigned)__cvta_generic_to_shared(sm);
    const unsigned bf0 = smu + F32_B;

    if (tid < W_MAX) s_band[tid] = 0.f;

    const int rl = lane & 7, gg = lane >> 3;
    const int arow  = 16 * warp + rl + ((gg & 1) << 3);
    const int acol0 = (gg >> 1) << 3;
    const int brow0 = 16 * warp + rl + ((gg >> 1) << 3);
    const int bcol0 = (gg & 1) << 3;

    int u  = (int)(((long)gB * UNITS) / NCTA);
    const int u1 = (int)(((long)(gB + 1) * UNITS) / NCTA);

    float c[15][4];

    while (u < u1) {
        const int tile = u / NCHT;
        const int cbeg = u % NCHT;
        const int cend = (cbeg + (u1 - u) < NCHT) ? cbeg + (u1 - u) : NCHT;
        const int R0   = tile * 128;
        u += cend - cbeg;

        #pragma unroll
        for (int i = 0; i < 15; i++)
            #pragma unroll
            for (int q = 0; q < 4; q++) c[i][q] = 0.f;

        auto load_f32 = [&](int ci) {
            #pragma unroll
            for (int k = 0; k < 8; k++) {
                int sid = tid + (k << 8);
                if (sid < RB * 8) {
                    int row = sid >> 3;
                    int seg = sid & 7;
                    int gr  = R0 + row;
                    int c4  = ci * 8 + seg;
                    unsigned ok = (gr < T_DIM && c4 < (D_DIM / 4)) ? 16u : 0u;
                    const float* gp = vel + ((size_t)(gr < T_DIM ? gr : 0)) * D_DIM
                                          + (c4 < (D_DIM / 4) ? c4 : 0) * 4;
                    CPA16Z(smu + (unsigned)(row * 128 + seg * 16), gp, ok);
                }
            }
            asm volatile("cp.async.commit_group;" ::: "memory");
        };

        // per-thread convert of own staged slots; NO barrier required around it
        auto convert = [&](int stw) {
            const unsigned hib = F32_B + stw * STAGE_B;
            #pragma unroll 4
            for (int k = 0; k < 8; k++) {
                int sid = tid + (k << 8);
                if (sid < RB * 8) {
                    int row = sid >> 3;
                    int seg = sid & 7;
                    const float4 v = *reinterpret_cast<const float4*>(
                        sm + (row * 128 + seg * 16));
                    __nv_bfloat162 h01 = __float22bfloat162_rn(make_float2(v.x, v.y));
                    __nv_bfloat162 h23 = __float22bfloat162_rn(make_float2(v.z, v.w));
                    float l0 = v.x - __bfloat162float(h01.x);
                    float l1 = v.y - __bfloat162float(h01.y);
                    float l2 = v.z - __bfloat162float(h23.x);
                    float l3 = v.w - __bfloat162float(h23.y);
                    __nv_bfloat162 q01 = __float22bfloat162_rn(make_float2(l0, l1));
                    __nv_bfloat162 q23 = __float22bfloat162_rn(make_float2(l2, l3));
                    uint2 hh, ll;
                    hh.x = *reinterpret_cast<unsigned*>(&h01);
                    hh.y = *reinterpret_cast<unsigned*>(&h23);
                    ll.x = *reinterpret_cast<unsigned*>(&q01);
                    ll.y = *reinterpret_cast<unsigned*>(&q23);
                    unsigned off = (unsigned)(row * STRB + seg * 8);
                    *reinterpret_cast<uint2*>(sm + hib + off) = hh;
                    *reinterpret_cast<uint2*>(sm + hib + HTILE_B + off) = ll;
                }
            }
        };

        // B-tile compute step for one (ks, njp)
        auto bstep = [&](unsigned hib, unsigned lob, int kk, int njp,
                         unsigned* ahi, unsigned* alo) {
            unsigned boff = (unsigned)((brow0 + njp * 16) * STRB + (kk + bcol0) * 2);
            unsigned bhi[4], blo[4];
            ldsm4(hib + boff, bhi[0], bhi[1], bhi[2], bhi[3]);
            ldsm4(lob + boff, blo[0], blo[1], blo[2], blo[3]);
            const int nj0 = njp * 2;
            mma16816(c[nj0], ahi, &bhi[0]);
            if (nj0 + 1 < 15) mma16816(c[nj0 + 1], ahi, &bhi[2]);
            mma16816(c[nj0], ahi, &blo[0]);
            if (nj0 + 1 < 15) mma16816(c[nj0 + 1], ahi, &blo[2]);
            mma16816(c[nj0], alo, &bhi[0]);
            if (nj0 + 1 < 15) mma16816(c[nj0 + 1], alo, &bhi[2]);
        };

        // ---- prologue ----
        load_f32(cbeg);
        asm volatile("cp.async.wait_group 0;" ::: "memory");
        convert(0);
        if (cbeg + 1 < cend) load_f32(cbeg + 1);
        __syncthreads();

        for (int ci = cbeg; ci < cend; ci++) {
            const int st  = (ci - cbeg) & 1;
            const unsigned hib = bf0 + st * STAGE_B;
            const unsigned lob = hib + HTILE_B;

            // ks = 0, njp 0..2
            {
                unsigned aoff = (unsigned)(arow * STRB + acol0 * 2);
                unsigned ahi[4], alo[4];
                ldsm4(hib + aoff, ahi[0], ahi[1], ahi[2], ahi[3]);
                ldsm4(lob + aoff, alo[0], alo[1], alo[2], alo[3]);
                #pragma unroll
                for (int njp = 0; njp < 3; njp++)
                    bstep(hib, lob, 0, njp, ahi, alo);

                // convert next chunk at a fragment-quiet point (no barrier!)
                if (ci + 1 < cend) {
                    asm volatile("cp.async.wait_group 0;" ::: "memory");
                    convert(st ^ 1);
                    if (ci + 2 < cend) load_f32(ci + 2);
                }

                #pragma unroll
                for (int njp = 3; njp < 8; njp++)
                    bstep(hib, lob, 0, njp, ahi, alo);
            }
            // ks = 1, njp 0..7
            {
                unsigned aoff = (unsigned)(arow * STRB + (16 + acol0) * 2);
                unsigned ahi[4], alo[4];
                ldsm4(hib + aoff, ahi[0], ahi[1], ahi[2], ahi[3]);
                ldsm4(lob + aoff, alo[0], alo[1], alo[2], alo[3]);
                #pragma unroll
                for (int njp = 0; njp < 8; njp++)
                    bstep(hib, lob, 16, njp, ahi, alo);
            }

            // single barrier: publishes convert STS, retires ldsm of stage[st]
            __syncthreads();
        }

        // ---- segment epilogue: band extraction ----
        #pragma unroll
        for (int nj = 0; nj < 15; nj++)
            #pragma unroll
            for (int q = 0; q < 4; q++) {
                int t = nj * 8 + ((lane & 3) << 1) + (q & 1)
                      - (lane >> 2) - ((q >> 1) << 3);
                if (t >= 0 && t < W_MAX) atomicAdd(&s_band[t], c[nj][q]);
            }
        __syncthreads();
        if (tid < W_MAX) {
            atomicAdd(&g_band[tid], (double)s_band[tid]);
            s_band[tid] = 0.f;
        }
        __syncthreads();
    }

    // ---- completion protocol: last CTA finalizes ----
    if (tid == 0) {
        __threadfence();
        unsigned p = atomicAdd(&g_done, 1u);
        s_last = (p == NCTA - 1);
    }
    __syncthreads();
    if (s_last) {
        __threadfence();
        if (tid < W_MAX && tid < W)
            out[tid] = (float)(g_band[tid] / ((double)(T_DIM - tid) * (double)D_DIM));
        if (tid < 128) g_band[tid] = 0.0;
        if (tid == 0) g_done = 0;
    }
}

extern "C" void kernel_launch(void* const* d_in, const int* in_sizes, int n_in,
                              void* d_out, int out_size) {
    const float* vel = (const float*)d_in[0];
    cudaFuncSetAttribute(vacf_gram, cudaFuncAttributeMaxDynamicSharedMemorySize, SMEM_B);
    vacf_gram<<<NCTA, 256, SMEM_B>>>(vel, (float*)d_out, out_size);
}

// round 8
// speedup vs baseline: 1.0542x; 1.0065x over previous
#include <cuda_runtime.h>
#include <cuda_bf16.h>
#include <cstdint>

// VACF via band-Gram, parallelogram tiling on mma.sync bf16.
// 512 threads / CTA, 1 CTA/SM, 148 CTAs. Each 16-row strip's 15-tile band is
// split between two warps (tiles 0-7 / 8-14) -> 32 accumulator regs/thread,
// no spills. Fused f32->bf16 split conversion at fragment-quiet points.
// S[t] = sum_i x_i . x_{i+t}; x = hi + lo (bf16); 3 passes hh+hl+lh.

#define T_DIM 10000
#define D_DIM 3000
#define NTILE 79                 // row tiles of 128
#define NCHT  94                 // K chunks of 32 elems
#define UNITS (NTILE * NCHT)     // 7426
#define NCTA  148
#define NTHREADS 512
#define W_MAX 100
#define RB    240                // rows per tile (128 + halo)
#define F32_B   (RB * 128)       // 30720 f32 staging
#define STRB    80               // bf16 smem row stride
#define HTILE_B (RB * STRB)      // 19200
#define STAGE_B (2 * HTILE_B)    // hi + lo
#define SMEM_B  (F32_B + 2 * STAGE_B)   // 107520

__device__ double g_band[128];       // zero-init; finalizer re-zeroes
__device__ unsigned g_done;          // zero-init; finalizer re-zeroes

__device__ __forceinline__ void ldsm4(unsigned a, unsigned& r0, unsigned& r1,
                                      unsigned& r2, unsigned& r3) {
    asm volatile("ldmatrix.sync.aligned.m8n8.x4.shared.b16 {%0,%1,%2,%3}, [%4];"
                 : "=r"(r0), "=r"(r1), "=r"(r2), "=r"(r3) : "r"(a));
}

__device__ __forceinline__ void mma16816(float* c, const unsigned* a, const unsigned* b) {
    asm("mma.sync.aligned.m16n8k16.row.col.f32.bf16.bf16.f32 "
        "{%0,%1,%2,%3}, {%4,%5,%6,%7}, {%8,%9}, {%0,%1,%2,%3};"
        : "+f"(c[0]), "+f"(c[1]), "+f"(c[2]), "+f"(c[3])
        : "r"(a[0]), "r"(a[1]), "r"(a[2]), "r"(a[3]), "r"(b[0]), "r"(b[1]));
}

#define CPA16Z(dst, src, z) \
    asm volatile("cp.async.cg.shared.global [%0], [%1], 16, %2;" \
                 :: "r"(dst), "l"(src), "r"(z))

__global__ __launch_bounds__(NTHREADS, 1) void vacf_gram(const float* __restrict__ vel,
                                                         float* __restrict__ out, int W) {
    extern __shared__ __align__(128) char sm[];
    __shared__ float s_band[W_MAX];
    __shared__ int s_last;

    const int tid  = threadIdx.x;
    const int warp = tid >> 5;
    const int lane = tid & 31;
    const int gB   = blockIdx.x;

    const unsigned smu = (unsigned)__cvta_generic_to_shared(sm);
    const unsigned bf0 = smu + F32_B;

    if (tid < W_MAX) s_band[tid] = 0.f;

    const int strip = warp >> 1;            // 0..7: 16-row strip
    const int njpb  = (warp & 1) * 4;       // band half: njp base 0 or 4
    const int rl = lane & 7, gg = lane >> 3;
    const int arow  = 16 * strip + rl + ((gg & 1) << 3);
    const int acol0 = (gg >> 1) << 3;
    const int brow0 = 16 * strip + rl + ((gg >> 1) << 3);
    const int bcol0 = (gg & 1) << 3;

    int u  = (int)(((long)gB * UNITS) / NCTA);
    const int u1 = (int)(((long)(gB + 1) * UNITS) / NCTA);

    float c[8][4];                          // 4 njp-pairs x 2 tiles x 4

    while (u < u1) {
        const int tile = u / NCHT;
        const int cbeg = u % NCHT;
        const int cend = (cbeg + (u1 - u) < NCHT) ? cbeg + (u1 - u) : NCHT;
        const int R0   = tile * 128;
        u += cend - cbeg;

        #pragma unroll
        for (int i = 0; i < 8; i++)
            #pragma unroll
            for (int q = 0; q < 4; q++) c[i][q] = 0.f;

        auto load_f32 = [&](int ci) {
            #pragma unroll
            for (int k = 0; k < 4; k++) {
                int sid = tid + (k << 9);
                if (sid < RB * 8) {
                    int row = sid >> 3;
                    int seg = sid & 7;
                    int gr  = R0 + row;
                    int c4  = ci * 8 + seg;
                    unsigned ok = (gr < T_DIM && c4 < (D_DIM / 4)) ? 16u : 0u;
                    const float* gp = vel + ((size_t)(gr < T_DIM ? gr : 0)) * D_DIM
                                          + (c4 < (D_DIM / 4) ? c4 : 0) * 4;
                    CPA16Z(smu + (unsigned)(row * 128 + seg * 16), gp, ok);
                }
            }
            asm volatile("cp.async.commit_group;" ::: "memory");
        };

        // per-thread convert of own staged slots; no barrier needed around it
        auto convert = [&](int stw) {
            const unsigned hib = F32_B + stw * STAGE_B;
            #pragma unroll 2
            for (int k = 0; k < 4; k++) {
                int sid = tid + (k << 9);
                if (sid < RB * 8) {
                    int row = sid >> 3;
                    int seg = sid & 7;
                    const float4 v = *reinterpret_cast<const float4*>(
                        sm + (row * 128 + seg * 16));
                    __nv_bfloat162 h01 = __float22bfloat162_rn(make_float2(v.x, v.y));
                    __nv_bfloat162 h23 = __float22bfloat162_rn(make_float2(v.z, v.w));
                    float l0 = v.x - __bfloat162float(h01.x);
                    float l1 = v.y - __bfloat162float(h01.y);
                    float l2 = v.z - __bfloat162float(h23.x);
                    float l3 = v.w - __bfloat162float(h23.y);
                    __nv_bfloat162 q01 = __float22bfloat162_rn(make_float2(l0, l1));
                    __nv_bfloat162 q23 = __float22bfloat162_rn(make_float2(l2, l3));
                    uint2 hh, ll;
                    hh.x = *reinterpret_cast<unsigned*>(&h01);
                    hh.y = *reinterpret_cast<unsigned*>(&h23);
                    ll.x = *reinterpret_cast<unsigned*>(&q01);
                    ll.y = *reinterpret_cast<unsigned*>(&q23);
                    unsigned off = (unsigned)(row * STRB + seg * 8);
                    *reinterpret_cast<uint2*>(sm + hib + off) = hh;
                    *reinterpret_cast<uint2*>(sm + hib + HTILE_B + off) = ll;
                }
            }
        };

        // one (ks, jl) B-step; local accumulator pair (2jl, 2jl+1)
        auto bstep = [&](unsigned hib, unsigned lob, int kk, int jl,
                         unsigned* ahi, unsigned* alo) {
            const int njp = njpb + jl;
            unsigned boff = (unsigned)((brow0 + njp * 16) * STRB + (kk + bcol0) * 2);
            unsigned bhi[4], blo[4];
            ldsm4(hib + boff, bhi[0], bhi[1], bhi[2], bhi[3]);
            ldsm4(lob + boff, blo[0], blo[1], blo[2], blo[3]);
            const int lj = jl * 2;
            const bool has2 = (njp * 2 + 1) < 15;
            mma16816(c[lj], ahi, &bhi[0]);
            if (has2) mma16816(c[lj + 1], ahi, &bhi[2]);
            mma16816(c[lj], ahi, &blo[0]);
            if (has2) mma16816(c[lj + 1], ahi, &blo[2]);
            mma16816(c[lj], alo, &bhi[0]);
            if (has2) mma16816(c[lj + 1], alo, &bhi[2]);
        };

        // ---- prologue ----
        load_f32(cbeg);
        asm volatile("cp.async.wait_group 0;" ::: "memory");
        convert(0);
        if (cbeg + 1 < cend) load_f32(cbeg + 1);
        __syncthreads();

        for (int ci = cbeg; ci < cend; ci++) {
            const int st  = (ci - cbeg) & 1;
            const unsigned hib = bf0 + st * STAGE_B;
            const unsigned lob = hib + HTILE_B;

            // ks = 0
            {
                unsigned aoff = (unsigned)(arow * STRB + acol0 * 2);
                unsigned ahi[4], alo[4];
                ldsm4(hib + aoff, ahi[0], ahi[1], ahi[2], ahi[3]);
                ldsm4(lob + aoff, alo[0], alo[1], alo[2], alo[3]);
                #pragma unroll
                for (int jl = 0; jl < 4; jl++)
                    bstep(hib, lob, 0, jl, ahi, alo);
            }

            // convert next chunk at a fragment-quiet point (no barrier)
            if (ci + 1 < cend) {
                asm volatile("cp.async.wait_group 0;" ::: "memory");
                convert(st ^ 1);
                if (ci + 2 < cend) load_f32(ci + 2);
            }

            // ks = 1
            {
                unsigned aoff = (unsigned)(arow * STRB + (16 + acol0) * 2);
                unsigned ahi[4], alo[4];
                ldsm4(hib + aoff, ahi[0], ahi[1], ahi[2], ahi[3]);
                ldsm4(lob + aoff, alo[0], alo[1], alo[2], alo[3]);
                #pragma unroll
                for (int jl = 0; jl < 4; jl++)
                    bstep(hib, lob, 16, jl, ahi, alo);
            }

            // single barrier: publishes convert STS, retires ldsm of stage[st]
            __syncthreads();
        }

        // ---- segment epilogue: band extraction ----
        #pragma unroll
        for (int jl = 0; jl < 4; jl++)
            #pragma unroll
            for (int j = 0; j < 2; j++) {
                const int nj = (njpb + jl) * 2 + j;
                if (nj < 15)
                    #pragma unroll
                    for (int q = 0; q < 4; q++) {
                        int t = nj * 8 + ((lane & 3) << 1) + (q & 1)
                              - (lane >> 2) - ((q >> 1) << 3);
                        if (t >= 0 && t < W_MAX)
                            atomicAdd(&s_band[t], c[jl * 2 + j][q]);
                    }
            }
        __syncthreads();
        if (tid < W_MAX) {
            atomicAdd(&g_band[tid], (double)s_band[tid]);
            s_band[tid] = 0.f;
        }
        __syncthreads();
    }

    // ---- completion protocol: last CTA finalizes ----
    if (tid == 0) {
        __threadfence();
        unsigned p = atomicAdd(&g_done, 1u);
        s_last = (p == NCTA - 1);
    }
    __syncthreads();
    if (s_last) {
        __threadfence();
        if (tid < W_MAX && tid < W)
            out[tid] = (float)(g_band[tid] / ((double)(T_DIM - tid) * (double)D_DIM));
        if (tid < 128) g_band[tid] = 0.0;
        if (tid == 0) g_done = 0;
    }
}

extern "C" void kernel_launch(void* const* d_in, const int* in_sizes, int n_in,
                              void* d_out, int out_size) {
    const float* vel = (const float*)d_in[0];
    cudaFuncSetAttribute(vacf_gram, cudaFuncAttributeMaxDynamicSharedMemorySize, SMEM_B);
    vacf_gram<<<NCTA, NTHREADS, SMEM_B>>>(vel, (float*)d_out, out_size);
}